// round 12
// baseline (speedup 1.0000x reference)
#include <cuda_runtime.h>
#include <cuda_bf16.h>
#include <math.h>

// Problem dims (fixed)
#define HH 768
#define G3 2304          // 3*H
#define BB 64            // batch
#define LL 512           // seq len
#define NSTEP 513        // 512 steps + final end-token step
#define NROWS (NSTEP*BB)

// recurrence kernel config (R7-proven tile)
#define RBLK 128         // persistent blocks
#define RTPB 256
#define UPB  6           // hidden units per block (128*6=768)
#define RC   18          // gh cols per block = 3*UPB
#define RCP  24          // padded ws row: 2 groups x 12 (9 used)
#define CHK  256         // staged k rows per chunk (768 = 3*256)

// Scratch (device globals — allocation-free rule)
static __device__ __align__(256) float g_giT[(size_t)NROWS * G3];  // gi transposed: [l][G3 unit][64 b]
static __device__ __align__(256) float g_h2[2][HH * BB];           // ping-pong h transposed [k][b]
static __device__ __align__(256) float g_hbm[BB * HH];             // final h [b][k] for scorer
static __device__ __align__(256) float g_s1[BB * HH];
static __device__ __align__(256) float g_s2[BB * HH];
static __device__ unsigned g_flag[3];                              // per-chunk arrival counters

// ---------------------------------------------------------------------------
// packed fp32 helpers (sm_103a f32x2)
__device__ __forceinline__ void ffma2(unsigned long long& d,
                                      unsigned long long a, unsigned long long b)
{
    asm("fma.rn.f32x2 %0, %1, %2, %0;" : "+l"(d) : "l"(a), "l"(b));
}
__device__ __forceinline__ unsigned long long pack2(float x)
{
    unsigned long long r;
    asm("mov.b64 %0, {%1, %1};" : "=l"(r) : "f"(x));
    return r;
}
__device__ __forceinline__ float2 unpk2(unsigned long long v)
{
    float2 f;
    asm("mov.b64 {%0, %1}, %2;" : "=f"(f.x), "=f"(f.y) : "l"(v));
    return f;
}
__device__ __forceinline__ void cpa16(unsigned dst, const void* src)
{
    asm volatile("cp.async.cg.shared.global [%0], [%1], 16;" :: "r"(dst), "l"(src));
}
__device__ __forceinline__ void cpa_commit() { asm volatile("cp.async.commit_group;" ::: "memory"); }
__device__ __forceinline__ void cpa_wait0()  { asm volatile("cp.async.wait_group 0;" ::: "memory"); }
__device__ __forceinline__ void cpa_wait1()  { asm volatile("cp.async.wait_group 1;" ::: "memory"); }

__device__ __forceinline__ float sigmoidf_(float x)
{
    return 1.f / (1.f + __expf(-x));
}

// ---------------------------------------------------------------------------
__global__ void k_init()
{
    int t = blockIdx.x * blockDim.x + threadIdx.x;
    if (t < BB * HH) g_h2[0][t] = 0.f;
    if (t < 3) g_flag[t] = 0u;
}

// ---------------------------------------------------------------------------
// giT[l][unit][b] = relu_if_seq(emb[token(b,l)]) . w_ih[unit,:] + b_ih[unit]
// (identical to R7 — proven)
__global__ void __launch_bounds__(128) k_gi(const int* __restrict__ goal,
                                            const float* __restrict__ emb,
                                            const float* __restrict__ w_ih,
                                            const float* __restrict__ b_ih)
{
    __shared__ __align__(16) float As[16][128];   // units x k
    __shared__ __align__(16) float Bs[16][64];    // batch x k
    __shared__ int tok[64];

    const int by  = blockIdx.y;        // step index
    const int n0  = blockIdx.x * 128;  // unit base
    const int tid = threadIdx.x;
    const bool seq = (by < LL);

    if (tid < 64) tok[tid] = seq ? goal[tid * LL + by] : 1;
    __syncthreads();

    const int ug = tid & 15;           // unit group -> units ug*8..+7
    const int bg = tid >> 4;           // batch group -> batch bg*8..+7

    float4 vw[4], ve[2];
    auto loadW = [&](float4 v[4], int k0) {
#pragma unroll
        for (int q = 0; q < 4; q++) {
            int f = tid + 128 * q;
            int r = f >> 2, kk = (f & 3) * 4;
            v[q] = *(const float4*)(w_ih + (size_t)(n0 + r) * HH + k0 + kk);
        }
    };
    auto loadE = [&](float4 v[2], int k0) {
#pragma unroll
        for (int q = 0; q < 2; q++) {
            int f = tid + 128 * q;
            int r = f >> 2, kk = (f & 3) * 4;
            v[q] = *(const float4*)(emb + (size_t)tok[r] * HH + k0 + kk);
            if (seq) {
                v[q].x = fmaxf(v[q].x, 0.f); v[q].y = fmaxf(v[q].y, 0.f);
                v[q].z = fmaxf(v[q].z, 0.f); v[q].w = fmaxf(v[q].w, 0.f);
            }
        }
    };
    auto storeW = [&](const float4 v[4]) {
#pragma unroll
        for (int q = 0; q < 4; q++) {
            int f = tid + 128 * q;
            int r = f >> 2, kk = (f & 3) * 4;
            As[kk][r] = v[q].x; As[kk+1][r] = v[q].y; As[kk+2][r] = v[q].z; As[kk+3][r] = v[q].w;
        }
    };
    auto storeE = [&](const float4 v[2]) {
#pragma unroll
        for (int q = 0; q < 2; q++) {
            int f = tid + 128 * q;
            int r = f >> 2, kk = (f & 3) * 4;
            Bs[kk][r] = v[q].x; Bs[kk+1][r] = v[q].y; Bs[kk+2][r] = v[q].z; Bs[kk+3][r] = v[q].w;
        }
    };

    unsigned long long acc[4][8];
#pragma unroll
    for (int p = 0; p < 4; p++)
#pragma unroll
        for (int c = 0; c < 8; c++) acc[p][c] = 0ull;

    loadW(vw, 0); loadE(ve, 0);
    storeW(vw);   storeE(ve);
    __syncthreads();

    for (int t = 0; t < HH / 16; t++) {
        float4 nw[4], ne[2];
        if (t < HH / 16 - 1) { loadW(nw, (t + 1) * 16); loadE(ne, (t + 1) * 16); }
#pragma unroll 4
        for (int k = 0; k < 16; k++) {
            ulonglong2 a0 = *(const ulonglong2*)&As[k][ug * 8];
            ulonglong2 a1 = *(const ulonglong2*)&As[k][ug * 8 + 4];
            float4 e0 = *(const float4*)&Bs[k][bg * 8];
            float4 e1 = *(const float4*)&Bs[k][bg * 8 + 4];
            unsigned long long ap[4] = {a0.x, a0.y, a1.x, a1.y};
            unsigned long long bp[8] = {pack2(e0.x), pack2(e0.y), pack2(e0.z), pack2(e0.w),
                                        pack2(e1.x), pack2(e1.y), pack2(e1.z), pack2(e1.w)};
#pragma unroll
            for (int p = 0; p < 4; p++)
#pragma unroll
                for (int c = 0; c < 8; c++) ffma2(acc[p][c], ap[p], bp[c]);
        }
        __syncthreads();
        if (t < HH / 16 - 1) { storeW(nw); storeE(ne); }
        __syncthreads();
    }

    // epilogue: giT[(by*G3 + unit)*64 + batch] (+ per-unit bias)
#pragma unroll
    for (int p = 0; p < 4; p++) {
        const int u0 = n0 + ug * 8 + 2 * p;
        float bia0 = b_ih[u0], bia1 = b_ih[u0 + 1];
        float2 v[8];
#pragma unroll
        for (int c = 0; c < 8; c++) v[c] = unpk2(acc[p][c]);
        float* d0 = g_giT + ((size_t)by * G3 + u0) * BB + bg * 8;
        float* d1 = d0 + BB;
        *(float4*)(d0)     = make_float4(v[0].x + bia0, v[1].x + bia0, v[2].x + bia0, v[3].x + bia0);
        *(float4*)(d0 + 4) = make_float4(v[4].x + bia0, v[5].x + bia0, v[6].x + bia0, v[7].x + bia0);
        *(float4*)(d1)     = make_float4(v[0].y + bia1, v[1].y + bia1, v[2].y + bia1, v[3].y + bia1);
        *(float4*)(d1 + 4) = make_float4(v[4].y + bia1, v[5].y + bia1, v[6].y + bia1, v[7].y + bia1);
    }
}

// ---------------------------------------------------------------------------
// Persistent recurrence: NO global barrier. Per-chunk ready flags + ping-pong h.
// Writers of chunk c: blocks whose units intersect [256c, 256c+256):
//   c=0: blocks 0..42 (43), c=1: 42..85 (44), c=2: 85..127 (43)
// A block waits flag[c] >= l*NW[c] before staging chunk c of step l.
// Safety: gates of step l+1 require all flags at (l+1)*NW -> every block
// finished step-l gates -> all reads of buf[l&1] completed before it is
// overwritten by step-(l+1) writes (same parity appears only at step l+2 reads).
__global__ void __launch_bounds__(RTPB, 1) k_rec(const float* __restrict__ w_hh,
                                                 const float* __restrict__ b_hh)
{
    extern __shared__ __align__(16) float sm[];
    float* ws  = sm;                       // [768][24] padded
    float* hs  = sm + HH * RCP;            // 2 x [256][64] staging slots
    float* red = hs + CHK * BB;            // alias slot1: 8 x [64][18]
    float* ghs = hs + 2 * CHK * BB;        // [64][18]

    const int tid  = threadIdx.x;
    const int bid  = blockIdx.x;
    const int u0   = bid * UPB;
    const int w    = tid >> 5;             // warp = k-slice 0..7
    const int lane = tid & 31;
    const int rg   = lane & 15;            // rows rg*4..+3 (2 f32x2 pairs)
    const int cg   = lane >> 4;            // col group 0..1 -> cols cg*9..+8

    // chunks this block writes (straddlers touch two)
    const int cwA = (6 * bid) / CHK;
    const int cwB = (6 * bid + 5) / CHK;

    // preload w slice: ws[k*24 + g2*12 + c] = w_hh[(gate*768+u0+unit)][k], col=g2*9+c
    for (int idx = tid; idx < HH * RCP; idx += RTPB) {
        int k = idx / RCP, cc = idx - k * RCP;
        int g2 = cc / 12, c = cc - g2 * 12;
        float v = 0.f;
        if (c < 9) {
            int col = g2 * 9 + c;
            int gate = col / UPB, unit = col - gate * UPB;
            v = w_hh[(size_t)(gate * HH + u0 + unit) * HH + k];
        }
        ws[idx] = v;
    }
    float bh_r[2], bh_z[2], bh_n[2], hreg[2];
#pragma unroll
    for (int q = 0; q < 2; q++) {
        int t = tid + q * RTPB;
        hreg[q] = 0.f;
        if (t < BB * UPB) {
            int iu = t >> 6;
            bh_r[q] = b_hh[u0 + iu];
            bh_z[q] = b_hh[HH + u0 + iu];
            bh_n[q] = b_hh[2 * HH + u0 + iu];
        }
    }
    __syncthreads();

    const unsigned hsb = (unsigned)__cvta_generic_to_shared(hs);
    // stage chunk c (of h buf for step l) into pipeline slot s
    auto stage = [&](const float* hbuf, int c, int s) {
        const float4* src = (const float4*)(hbuf + (size_t)c * CHK * BB) + tid;
        unsigned dst = hsb + (unsigned)(s * (CHK * BB * 4)) + tid * 16;
#pragma unroll
        for (int j = 0; j < (CHK * BB / 4) / RTPB; j++)   // 16
            cpa16(dst + j * RTPB * 16, src + j * RTPB);
        cpa_commit();
    };
    auto flagwait = [&](int c, unsigned target) {
        if (tid == 0 && target) {
            unsigned v;
            for (;;) {
                asm volatile("ld.acquire.gpu.global.u32 %0, [%1];"
                             : "=r"(v) : "l"(g_flag + c) : "memory");
                if (v >= target) break;
                __nanosleep(20);
            }
        }
        __syncthreads();
    };

    const int c0 = bid % 3, c1 = (c0 + 1) % 3, c2 = (c0 + 2) % 3;

    for (int l = 0; l < NSTEP; l++) {
        const float* hbuf = g_h2[l & 1];
        const unsigned tgt = (unsigned)l;
        const unsigned nw0 = (c0 == 1) ? 44u : 43u;
        const unsigned nw1 = (c1 == 1) ? 44u : 43u;
        const unsigned nw2 = (c2 == 1) ? 44u : 43u;

        flagwait(c0, tgt * nw0);
        stage(hbuf, c0, 0);
        flagwait(c1, tgt * nw1);
        stage(hbuf, c1, 1);

        // prefetch gi operands (batch-contiguous; consumed at gate time)
        float pre_r[2], pre_z[2], pre_n[2];
#pragma unroll
        for (int q = 0; q < 2; q++) {
            int t = tid + q * RTPB;
            if (t < BB * UPB) {
                int b = t & 63, iu = t >> 6;
                const float* gp = g_giT + ((size_t)l * G3 + u0 + iu) * BB + b;
                pre_r[q] = __ldcg(gp);
                pre_z[q] = __ldcg(gp + (size_t)HH * BB);
                pre_n[q] = __ldcg(gp + (size_t)2 * HH * BB);
            }
        }

        unsigned long long acc[2][9];
#pragma unroll
        for (int p = 0; p < 2; p++)
#pragma unroll
            for (int c = 0; c < 9; c++) acc[p][c] = 0ull;

        auto compute = [&](int slot, int cch) {
            const float* hb = hs + slot * (CHK * BB);
            const int kb = w * (CHK / 8);
#pragma unroll 4
            for (int kk = 0; kk < CHK / 8; kk++) {
                const int kl = kb + kk;
                const int kg = cch * CHK + kl;
                ulonglong2 a = *(const ulonglong2*)&hb[kl * BB + rg * 4];
                const float* wp = &ws[kg * RCP + cg * 12];
                float4 w0 = *(const float4*)(wp);
                float4 w1 = *(const float4*)(wp + 4);
                float  w8 = wp[8];
                unsigned long long bp[9] = {pack2(w0.x), pack2(w0.y), pack2(w0.z), pack2(w0.w),
                                            pack2(w1.x), pack2(w1.y), pack2(w1.z), pack2(w1.w),
                                            pack2(w8)};
#pragma unroll
                for (int c = 0; c < 9; c++) {
                    ffma2(acc[0][c], a.x, bp[c]);
                    ffma2(acc[1][c], a.y, bp[c]);
                }
            }
        };

        cpa_wait1();  __syncthreads();
        compute(0, c0);
        __syncthreads();
        flagwait(c2, tgt * nw2);
        stage(hbuf, c2, 0);

        cpa_wait1();  __syncthreads();
        compute(1, c1);
        __syncthreads();                   // slot1 free -> red alias safe

        cpa_wait0();  __syncthreads();
        compute(0, c2);
        __syncthreads();

        // ---- k-split reduction: red[w][64][18] (slot1), then ghs[64][18] ----
#pragma unroll
        for (int p = 0; p < 2; p++) {
            const int r0 = rg * 4 + 2 * p;
#pragma unroll
            for (int c = 0; c < 9; c++) {
                float2 v = unpk2(acc[p][c]);
                red[w * (BB * RC) + r0 * RC + cg * 9 + c]       = v.x;
                red[w * (BB * RC) + (r0 + 1) * RC + cg * 9 + c] = v.y;
            }
        }
        __syncthreads();
#pragma unroll
        for (int j = 0; j < 5; j++) {                    // 1152 outputs / 256 thr
            const int o = tid + j * RTPB;
            if (o < BB * RC) {
                float s = red[o];
#pragma unroll
                for (int ww = 1; ww < 8; ww++) s += red[ww * (BB * RC) + o];
                ghs[o] = s;
            }
        }
        __syncthreads();

        // ---- gates (block-local; own h kept in registers) ----
        float* hout = g_h2[(l + 1) & 1];
#pragma unroll
        for (int q = 0; q < 2; q++) {
            const int t = tid + q * RTPB;
            if (t < BB * UPB) {
                const int b = t & 63, iu = t >> 6;
                float ghr = ghs[b * RC + iu];
                float ghz = ghs[b * RC + UPB + iu];
                float ghn = ghs[b * RC + 2 * UPB + iu];
                float r = sigmoidf_(pre_r[q] + ghr + bh_r[q]);
                float z = sigmoidf_(pre_z[q] + ghz + bh_z[q]);
                float n = tanhf(pre_n[q] + r * (ghn + bh_n[q]));
                float h = (1.f - z) * n + z * hreg[q];
                if (l < LL) h = fmaxf(h, 0.f);     // final step NOT relu'd
                hreg[q] = h;
                __stcg(&hout[(u0 + iu) * BB + b], h);
                if (l == LL) g_hbm[(size_t)b * HH + u0 + iu] = h;
            }
        }

        // publish: stores -> sync -> fence -> arrive at owned chunk flag(s)
        __syncthreads();
        if (tid == 0) {
            __threadfence();
            atomicAdd(&g_flag[cwA], 1u);
            if (cwB != cwA) atomicAdd(&g_flag[cwB], 1u);
        }
    }
}

// ---------------------------------------------------------------------------
// Scorer: warp-per-neuron, weights in registers; device globals referenced
// directly in device code (host may not pass __device__ symbols).
__global__ void __launch_bounds__(256) k_mlp0(const float* __restrict__ w,
                                              const float* __restrict__ bias)
{
    const int warp = threadIdx.x >> 5;
    const int lane = threadIdx.x & 31;
    const int n = blockIdx.x * 8 + warp;

    float4 wr[6];
    const float* wrow = w + (size_t)n * HH + lane * 24;
#pragma unroll
    for (int i = 0; i < 6; i++) wr[i] = *(const float4*)(wrow + i * 4);
    const float bn = bias[n];

    for (int b = 0; b < BB; b++) {
        const float* xr = g_hbm + (size_t)b * HH + lane * 24;
        float s = 0.f;
#pragma unroll
        for (int i = 0; i < 6; i++) {
            float4 xv = *(const float4*)(xr + i * 4);
            s += xv.x * wr[i].x + xv.y * wr[i].y + xv.z * wr[i].z + xv.w * wr[i].w;
        }
#pragma unroll
        for (int off = 16; off; off >>= 1) s += __shfl_xor_sync(0xffffffffu, s, off);
        if (lane == 0) g_s1[(size_t)b * HH + n] = fmaxf(s + bn, 0.f);
    }
}

__global__ void __launch_bounds__(256) k_mlp1(const float* __restrict__ w,
                                              const float* __restrict__ bias)
{
    const int warp = threadIdx.x >> 5;
    const int lane = threadIdx.x & 31;
    const int n = blockIdx.x * 8 + warp;

    float4 wr[6];
    const float* wrow = w + (size_t)n * HH + lane * 24;
#pragma unroll
    for (int i = 0; i < 6; i++) wr[i] = *(const float4*)(wrow + i * 4);
    const float bn = bias[n];

    for (int b = 0; b < BB; b++) {
        const float* xr = g_s1 + (size_t)b * HH + lane * 24;
        float s = 0.f;
#pragma unroll
        for (int i = 0; i < 6; i++) {
            float4 xv = *(const float4*)(xr + i * 4);
            s += xv.x * wr[i].x + xv.y * wr[i].y + xv.z * wr[i].z + xv.w * wr[i].w;
        }
#pragma unroll
        for (int off = 16; off; off >>= 1) s += __shfl_xor_sync(0xffffffffu, s, off);
        if (lane == 0) g_s2[(size_t)b * HH + n] = fmaxf(s + bn, 0.f);
    }
}

__global__ void __launch_bounds__(256) k_final(const float* __restrict__ swo,
                                               const float* __restrict__ sbo,
                                               float* __restrict__ out)
{
    const int warp = threadIdx.x >> 5;
    const int lane = threadIdx.x & 31;
    const int b = blockIdx.x * 8 + warp;
    const float* xr = g_s2 + (size_t)b * HH + lane * 24;
    const float* wr = swo + lane * 24;
    float s = 0.f;
#pragma unroll
    for (int i = 0; i < 6; i++) {
        float4 xv = *(const float4*)(xr + i * 4);
        float4 wv = *(const float4*)(wr + i * 4);
        s += xv.x * wv.x + xv.y * wv.y + xv.z * wv.z + xv.w * wv.w;
    }
#pragma unroll
    for (int off = 16; off; off >>= 1) s += __shfl_xor_sync(0xffffffffu, s, off);
    if (lane == 0) out[b] = s + sbo[0];
}

// ---------------------------------------------------------------------------
extern "C" void kernel_launch(void* const* d_in, const int* in_sizes, int n_in,
                              void* d_out, int out_size)
{
    const int*   goal = (const int*)  d_in[0];
    const float* emb  = (const float*)d_in[1];
    const float* w_ih = (const float*)d_in[2];
    const float* w_hh = (const float*)d_in[3];
    const float* b_ih = (const float*)d_in[4];
    const float* b_hh = (const float*)d_in[5];
    const float* sw0  = (const float*)d_in[6];
    const float* sb0  = (const float*)d_in[7];
    const float* sw1  = (const float*)d_in[8];
    const float* sb1  = (const float*)d_in[9];
    const float* swo  = (const float*)d_in[10];
    const float* sbo  = (const float*)d_in[11];
    float* out = (float*)d_out;

    const int smem_rec = (HH * RCP + 2 * CHK * BB + BB * RC) * (int)sizeof(float); // 204.5KB
    cudaFuncSetAttribute(k_rec, cudaFuncAttributeMaxDynamicSharedMemorySize, smem_rec);

    k_init<<<(BB * HH + 255) / 256, 256>>>();
    k_gi<<<dim3(G3 / 128, NSTEP), 128>>>(goal, emb, w_ih, b_ih);
    k_rec<<<RBLK, RTPB, smem_rec>>>(w_hh, b_hh);
    k_mlp0<<<HH / 8, 256>>>(sw0, sb0);
    k_mlp1<<<HH / 8, 256>>>(sw1, sb1);
    k_final<<<BB / 8, 256>>>(swo, sbo, out);
}

// round 14
// speedup vs baseline: 1.2489x; 1.2489x over previous
#include <cuda_runtime.h>
#include <cuda_bf16.h>
#include <math.h>
#include <stdint.h>

// Problem dims (fixed)
#define HH 768
#define G3 2304          // 3*H
#define BB 64            // batch
#define VV 32000         // vocab
#define LL 512           // seq len
#define NSTEP 513        // 512 steps + final end-token step
#define NROWS (NSTEP*BB)

// recurrence kernel config (R7-proven, benched 7994us)
#define RBLK 128
#define RTPB 256
#define UPB  6
#define RC   18
#define RCP  24
#define CHK  256

// gi tensor kernel
#define ASTR 72          // padded smem row stride (bf16) for ldmatrix
#define GI_SMEM ((128*ASTR + 128*ASTR + 64*ASTR + 64*ASTR) * 2)   // 55296B

// Scratch (device globals — allocation-free rule)
static __device__ __align__(256) float g_giT[(size_t)NROWS * G3];    // [l][unit][b]
static __device__ __align__(256) float g_hT[HH * BB];                // h transposed [k][b]
static __device__ __align__(256) float g_hbm[BB * HH];
static __device__ __align__(256) float g_s1[BB * HH];
static __device__ __align__(256) float g_s2[BB * HH];
static __device__ __align__(256) __nv_bfloat16 g_wih_h[(size_t)G3 * HH];
static __device__ __align__(256) __nv_bfloat16 g_wih_l[(size_t)G3 * HH];
static __device__ __align__(256) __nv_bfloat16 g_emb_h[(size_t)VV * HH];  // relu'd
static __device__ __align__(256) __nv_bfloat16 g_emb_l[(size_t)VV * HH];
static __device__ __align__(256) __nv_bfloat16 g_end_h[HH];               // emb[1], NO relu
static __device__ __align__(256) __nv_bfloat16 g_end_l[HH];
static __device__ unsigned g_leaf[16];
static __device__ unsigned g_master = 0;
static __device__ unsigned g_gen    = 0;

// ---------------------------------------------------------------------------
// packed fp32 helpers (sm_103a f32x2)
__device__ __forceinline__ void ffma2(unsigned long long& d,
                                      unsigned long long a, unsigned long long b)
{
    asm("fma.rn.f32x2 %0, %1, %2, %0;" : "+l"(d) : "l"(a), "l"(b));
}
__device__ __forceinline__ unsigned long long pack2(float x)
{
    unsigned long long r;
    asm("mov.b64 %0, {%1, %1};" : "=l"(r) : "f"(x));
    return r;
}
__device__ __forceinline__ float2 unpk2(unsigned long long v)
{
    float2 f;
    asm("mov.b64 {%0, %1}, %2;" : "=f"(f.x), "=f"(f.y) : "l"(v));
    return f;
}
__device__ __forceinline__ void cpa16(unsigned dst, const void* src)
{
    asm volatile("cp.async.cg.shared.global [%0], [%1], 16;" :: "r"(dst), "l"(src));
}
__device__ __forceinline__ void cpa_commit() { asm volatile("cp.async.commit_group;" ::: "memory"); }
__device__ __forceinline__ void cpa_wait0()  { asm volatile("cp.async.wait_group 0;" ::: "memory"); }
__device__ __forceinline__ void cpa_wait1()  { asm volatile("cp.async.wait_group 1;" ::: "memory"); }

__device__ __forceinline__ float sigmoidf_(float x)
{
    return 1.f / (1.f + __expf(-x));
}
__device__ __forceinline__ uint32_t smem_u32(const void* p)
{
    uint32_t a;
    asm("{ .reg .u64 t; cvta.to.shared.u64 t, %1; cvt.u32.u64 %0, t; }" : "=r"(a) : "l"(p));
    return a;
}
// mma.sync (sm_80+, no 'a' feature needed)
__device__ __forceinline__ void ldm4(uint32_t r[4], uint32_t addr)
{
    asm volatile("ldmatrix.sync.aligned.m8n8.x4.shared.b16 {%0,%1,%2,%3}, [%4];"
                 : "=r"(r[0]), "=r"(r[1]), "=r"(r[2]), "=r"(r[3]) : "r"(addr));
}
__device__ __forceinline__ void mma16816(float d[4], const uint32_t a[4],
                                         uint32_t b0, uint32_t b1)
{
    asm volatile("mma.sync.aligned.m16n8k16.row.col.f32.bf16.bf16.f32 "
                 "{%0,%1,%2,%3}, {%4,%5,%6,%7}, {%8,%9}, {%0,%1,%2,%3};"
                 : "+f"(d[0]), "+f"(d[1]), "+f"(d[2]), "+f"(d[3])
                 : "r"(a[0]), "r"(a[1]), "r"(a[2]), "r"(a[3]), "r"(b0), "r"(b1));
}
__device__ __forceinline__ void split_bf(float x, __nv_bfloat16& h, __nv_bfloat16& l)
{
    h = __float2bfloat16(x);
    l = __float2bfloat16(x - __bfloat162float(h));
}

// ---------------------------------------------------------------------------
__global__ void k_init()
{
    int t = blockIdx.x * blockDim.x + threadIdx.x;
    if (t < BB * HH) g_hT[t] = 0.f;
}

// precompute bf16 hi/lo tables
__global__ void k_prep_w(const float* __restrict__ w_ih)
{
    int t = blockIdx.x * blockDim.x + threadIdx.x;
    if (t < G3 * HH) split_bf(w_ih[t], g_wih_h[t], g_wih_l[t]);
}
__global__ void k_prep_e(const float* __restrict__ emb)
{
    size_t t = (size_t)blockIdx.x * blockDim.x + threadIdx.x;
    if (t < (size_t)VV * HH) {
        float x = fmaxf(emb[t], 0.f);           // relu'd table (seq steps)
        split_bf(x, g_emb_h[t], g_emb_l[t]);
    }
    if (t < HH) split_bf(emb[HH + t], g_end_h[t], g_end_l[t]);  // emb[1], no relu
}

// ---------------------------------------------------------------------------
// Tensor gi via mma.sync: CTA = (step by, 128-unit tile n0). M128 x N64 x K768.
// bf16x3: hi*hi + hi*lo + lo*hi. 8 warps, warp tile 32(M)x32(N).
__global__ void __launch_bounds__(256) k_gi_tc(const int* __restrict__ goal,
                                               const float* __restrict__ b_ih)
{
    extern __shared__ __align__(16) char dsm[];
    __nv_bfloat16* Ah = (__nv_bfloat16*)dsm;                    // [128][ASTR]
    __nv_bfloat16* Al = Ah + 128 * ASTR;
    __nv_bfloat16* Bh = Al + 128 * ASTR;                        // [64][ASTR]
    __nv_bfloat16* Bl = Bh + 64 * ASTR;
    __shared__ int tok[BB];

    const int tid  = threadIdx.x;
    const int wid  = tid >> 5;
    const int lane = tid & 31;
    const int by   = blockIdx.y;
    const int n0   = blockIdx.x * 128;
    const bool seq = (by < LL);
    const int wm   = wid & 3;          // M group: rows wm*32..+31
    const int wn   = wid >> 2;         // N group: cols wn*32..+31

    if (tid < BB) tok[tid] = seq ? goal[tid * LL + by] : 1;
    __syncthreads();

    const uint32_t aH = smem_u32(Ah), aL = smem_u32(Al);
    const uint32_t bH = smem_u32(Bh), bL = smem_u32(Bl);

    float acc[2][4][4];
#pragma unroll
    for (int mt = 0; mt < 2; mt++)
#pragma unroll
        for (int nt = 0; nt < 4; nt++)
#pragma unroll
            for (int i = 0; i < 4; i++) acc[mt][nt][i] = 0.f;

    // ldmatrix lane geometry (shared by A and B)
    const int mi = lane >> 3, ri = lane & 7;
    const int lrow = ri + (mi & 1) * 8;      // row offset within 16
    const int lcol = (mi >> 1) * 8;          // col offset within 16

    for (int ch = 0; ch < HH / 64; ch++) {
        const int k0 = ch * 64;
        // fill A (w_ih slice): 128 rows x 64 bf16, 8 x uint4 per row per table
#pragma unroll
        for (int t = 0; t < 4; t++) {
            int i = tid + t * 256;           // 0..1023
            int r = i >> 3, q = i & 7;
            size_t src = (size_t)(n0 + r) * HH + k0 + q * 8;
            *(uint4*)(Ah + r * ASTR + q * 8) = *(const uint4*)(g_wih_h + src);
            *(uint4*)(Al + r * ASTR + q * 8) = *(const uint4*)(g_wih_l + src);
        }
        // fill B (token rows): 64 rows x 64 bf16
#pragma unroll
        for (int t = 0; t < 2; t++) {
            int i = tid + t * 256;           // 0..511
            int r = i >> 3, q = i & 7;
            if (seq) {
                size_t src = (size_t)tok[r] * HH + k0 + q * 8;
                *(uint4*)(Bh + r * ASTR + q * 8) = *(const uint4*)(g_emb_h + src);
                *(uint4*)(Bl + r * ASTR + q * 8) = *(const uint4*)(g_emb_l + src);
            } else {
                *(uint4*)(Bh + r * ASTR + q * 8) = *(const uint4*)(g_end_h + k0 + q * 8);
                *(uint4*)(Bl + r * ASTR + q * 8) = *(const uint4*)(g_end_l + k0 + q * 8);
            }
        }
        __syncthreads();

#pragma unroll
        for (int ks = 0; ks < 4; ks++) {
            const int kk = ks * 16;
            // B frags: two n-pairs (n0-15, n16-31 of warp's 32)
            uint32_t bh0[4], bh1[4], bl0[4], bl1[4];
            {
                int nrow0 = wn * 32 + lrow, nrow1 = nrow0 + 16;
                uint32_t o0 = (uint32_t)(nrow0 * ASTR + kk + lcol) * 2;
                uint32_t o1 = (uint32_t)(nrow1 * ASTR + kk + lcol) * 2;
                ldm4(bh0, bH + o0); ldm4(bh1, bH + o1);
                ldm4(bl0, bL + o0); ldm4(bl1, bL + o1);
            }
#pragma unroll
            for (int mt = 0; mt < 2; mt++) {
                uint32_t ah[4], al[4];
                int arow = wm * 32 + mt * 16 + lrow;
                uint32_t ao = (uint32_t)(arow * ASTR + kk + lcol) * 2;
                ldm4(ah, aH + ao);
                ldm4(al, aL + ao);
                // ntile 0..3: pair = nt>>1 ? (bh1) : (bh0); within-pair sel nt&1:
                // x4 on rows n..n+15 gives m0=(n0-7,klo) m1=(n8-15,klo) m2=(n0-7,khi) m3=(n8-15,khi)
#pragma unroll
                for (int nt = 0; nt < 4; nt++) {
                    uint32_t* ph = (nt < 2) ? bh0 : bh1;
                    uint32_t* pl = (nt < 2) ? bl0 : bl1;
                    int s = nt & 1;
                    mma16816(acc[mt][nt], ah, ph[s], ph[s + 2]);   // hi*hi
                    mma16816(acc[mt][nt], ah, pl[s], pl[s + 2]);   // hi*lo
                    mma16816(acc[mt][nt], al, ph[s], ph[s + 2]);   // lo*hi
                }
            }
        }
        __syncthreads();
    }

    // epilogue: D row (unit) = wm*32 + mt*16 + {g, g+8}; col (batch) = wn*32 + nt*8 + 2t{,+1}
    const int g  = lane >> 2;
    const int t4 = lane & 3;
#pragma unroll
    for (int mt = 0; mt < 2; mt++) {
        const int u_lo = n0 + wm * 32 + mt * 16 + g;
        const float bia_lo = b_ih[u_lo], bia_hi = b_ih[u_lo + 8];
        float* base_lo = g_giT + ((size_t)by * G3 + u_lo) * BB;
        float* base_hi = base_lo + 8 * BB;
#pragma unroll
        for (int nt = 0; nt < 4; nt++) {
            const int bc = wn * 32 + nt * 8 + 2 * t4;
            *(float2*)(base_lo + bc) = make_float2(acc[mt][nt][0] + bia_lo,
                                                   acc[mt][nt][1] + bia_lo);
            *(float2*)(base_hi + bc) = make_float2(acc[mt][nt][2] + bia_hi,
                                                   acc[mt][nt][3] + bia_hi);
        }
    }
}

// ---------------------------------------------------------------------------
// Two-level grid barrier (verbatim from benched 7994us kernel)
__device__ __forceinline__ void gsync(unsigned target)
{
    __syncthreads();
    if (threadIdx.x == 0) {
        unsigned old;
        asm volatile("atom.acq_rel.gpu.global.add.u32 %0, [%1], %2;"
                     : "=r"(old) : "l"(g_leaf + (blockIdx.x & 15u)), "r"(1u) : "memory");
        if ((old & 7u) == 7u) {
            unsigned o2;
            asm volatile("atom.acq_rel.gpu.global.add.u32 %0, [%1], %2;"
                         : "=r"(o2) : "l"(&g_master), "r"(1u) : "memory");
            if ((o2 & 15u) == 15u)
                asm volatile("st.release.gpu.global.u32 [%0], %1;"
                             :: "l"(&g_gen), "r"(target) : "memory");
        }
        unsigned g;
        do {
            asm volatile("ld.acquire.gpu.global.u32 %0, [%1];"
                         : "=r"(g) : "l"(&g_gen) : "memory");
        } while ((int)(g - target) < 0);
    }
    __syncthreads();
}

// ---------------------------------------------------------------------------
// Persistent recurrence (verbatim R7, benched 7994us)
__global__ void __launch_bounds__(RTPB, 1) k_rec(const float* __restrict__ w_hh,
                                                 const float* __restrict__ b_hh)
{
    extern __shared__ __align__(16) float sm[];
    float* ws  = sm;
    float* hs  = sm + HH * RCP;
    float* red = hs + CHK * BB;
    float* ghs = hs + 2 * CHK * BB;

    const int tid  = threadIdx.x;
    const int u0   = blockIdx.x * UPB;
    const int w    = tid >> 5;
    const int lane = tid & 31;
    const int rg   = lane & 15;
    const int cg   = lane >> 4;

    for (int idx = tid; idx < HH * RCP; idx += RTPB) {
        int k = idx / RCP, cc = idx - k * RCP;
        int g2 = cc / 12, c = cc - g2 * 12;
        float v = 0.f;
        if (c < 9) {
            int col = g2 * 9 + c;
            int gate = col / UPB, unit = col - gate * UPB;
            v = w_hh[(size_t)(gate * HH + u0 + unit) * HH + k];
        }
        ws[idx] = v;
    }
    float bh_r[2], bh_z[2], bh_n[2];
#pragma unroll
    for (int q = 0; q < 2; q++) {
        int t = tid + q * RTPB;
        if (t < BB * UPB) {
            int iu = t >> 6;
            bh_r[q] = b_hh[u0 + iu];
            bh_z[q] = b_hh[HH + u0 + iu];
            bh_n[q] = b_hh[2 * HH + u0 + iu];
        }
    }
    __syncthreads();

    const unsigned hsb = (unsigned)__cvta_generic_to_shared(hs);
    auto stage = [&](int ch) {
        const float4* src = (const float4*)(g_hT + (size_t)ch * CHK * BB) + tid;
        unsigned dst = hsb + (unsigned)((ch & 1) * (CHK * BB * 4)) + tid * 16;
#pragma unroll
        for (int j = 0; j < (CHK * BB / 4) / RTPB; j++)
            cpa16(dst + j * RTPB * 16, src + j * RTPB);
        cpa_commit();
    };

    const unsigned base = *(volatile unsigned*)&g_gen;
    unsigned ngen = 0;

    for (int l = 0; l < NSTEP; l++) {
        stage(0);
        stage(1);

        float pre_r[2], pre_z[2], pre_n[2], pre_h[2];
#pragma unroll
        for (int q = 0; q < 2; q++) {
            int t = tid + q * RTPB;
            if (t < BB * UPB) {
                int b = t & 63, iu = t >> 6;
                const float* gp = g_giT + ((size_t)l * G3 + u0 + iu) * BB + b;
                pre_r[q] = __ldcg(gp);
                pre_z[q] = __ldcg(gp + (size_t)HH * BB);
                pre_n[q] = __ldcg(gp + (size_t)2 * HH * BB);
                pre_h[q] = __ldcg(&g_hT[(u0 + iu) * BB + b]);
            }
        }

        unsigned long long acc[2][9];
#pragma unroll
        for (int p = 0; p < 2; p++)
#pragma unroll
            for (int c = 0; c < 9; c++) acc[p][c] = 0ull;

        for (int ch = 0; ch < HH / CHK; ch++) {
            if (ch < HH / CHK - 1) cpa_wait1(); else cpa_wait0();
            __syncthreads();
            const float* hb = hs + (ch & 1) * (CHK * BB);
            const int kb = w * (CHK / 8);
#pragma unroll 4
            for (int kk = 0; kk < CHK / 8; kk++) {
                const int kl = kb + kk;
                const int kg = ch * CHK + kl;
                ulonglong2 a = *(const ulonglong2*)&hb[kl * BB + rg * 4];
                const float* wp = &ws[kg * RCP + cg * 12];
                float4 w0 = *(const float4*)(wp);
                float4 w1 = *(const float4*)(wp + 4);
                float  w8 = wp[8];
                unsigned long long bp[9] = {pack2(w0.x), pack2(w0.y), pack2(w0.z), pack2(w0.w),
                                            pack2(w1.x), pack2(w1.y), pack2(w1.z), pack2(w1.w),
                                            pack2(w8)};
#pragma unroll
                for (int c = 0; c < 9; c++) {
                    ffma2(acc[0][c], a.x, bp[c]);
                    ffma2(acc[1][c], a.y, bp[c]);
                }
            }
            __syncthreads();
            if (ch == 0) stage(2);
        }

#pragma unroll
        for (int p = 0; p < 2; p++) {
            const int r0 = rg * 4 + 2 * p;
#pragma unroll
            for (int c = 0; c < 9; c++) {
                float2 v = unpk2(acc[p][c]);
                red[w * (BB * RC) + r0 * RC + cg * 9 + c]       = v.x;
                red[w * (BB * RC) + (r0 + 1) * RC + cg * 9 + c] = v.y;
            }
        }
        __syncthreads();
#pragma unroll
        for (int j = 0; j < 5; j++) {
            const int o = tid + j * RTPB;
            if (o < BB * RC) {
                float s = red[o];
#pragma unroll
                for (int ww = 1; ww < 8; ww++) s += red[ww * (BB * RC) + o];
                ghs[o] = s;
            }
        }
        __syncthreads();

#pragma unroll
        for (int q = 0; q < 2; q++) {
            const int t = tid + q * RTPB;
            if (t < BB * UPB) {
                const int b = t & 63, iu = t >> 6;
                float ghr = ghs[b * RC + iu];
                float ghz = ghs[b * RC + UPB + iu];
                float ghn = ghs[b * RC + 2 * UPB + iu];
                float r = sigmoidf_(pre_r[q] + ghr + bh_r[q]);
                float z = sigmoidf_(pre_z[q] + ghz + bh_z[q]);
                float n = tanhf(pre_n[q] + r * (ghn + bh_n[q]));
                float h = (1.f - z) * n + z * pre_h[q];
                if (l < LL) h = fmaxf(h, 0.f);     // final step NOT relu'd
                __stcg(&g_hT[(u0 + iu) * BB + b], h);
                if (l == LL) g_hbm[(size_t)b * HH + u0 + iu] = h;
            }
        }

        ++ngen;
        gsync(base + ngen);
    }
}

// ---------------------------------------------------------------------------
// Scorer (verbatim)
__global__ void __launch_bounds__(256) k_mlp0(const float* __restrict__ w,
                                              const float* __restrict__ bias)
{
    const int warp = threadIdx.x >> 5;
    const int lane = threadIdx.x & 31;
    const int n = blockIdx.x * 8 + warp;

    float4 wr[6];
    const float* wrow = w + (size_t)n * HH + lane * 24;
#pragma unroll
    for (int i = 0; i < 6; i++) wr[i] = *(const float4*)(wrow + i * 4);
    const float bn = bias[n];

    for (int b = 0; b < BB; b++) {
        const float* xr = g_hbm + (size_t)b * HH + lane * 24;
        float s = 0.f;
#pragma unroll
        for (int i = 0; i < 6; i++) {
            float4 xv = *(const float4*)(xr + i * 4);
            s += xv.x * wr[i].x + xv.y * wr[i].y + xv.z * wr[i].z + xv.w * wr[i].w;
        }
#pragma unroll
        for (int off = 16; off; off >>= 1) s += __shfl_xor_sync(0xffffffffu, s, off);
        if (lane == 0) g_s1[(size_t)b * HH + n] = fmaxf(s + bn, 0.f);
    }
}

__global__ void __launch_bounds__(256) k_mlp1(const float* __restrict__ w,
                                              const float* __restrict__ bias)
{
    const int warp = threadIdx.x >> 5;
    const int lane = threadIdx.x & 31;
    const int n = blockIdx.x * 8 + warp;

    float4 wr[6];
    const float* wrow = w + (size_t)n * HH + lane * 24;
#pragma unroll
    for (int i = 0; i < 6; i++) wr[i] = *(const float4*)(wrow + i * 4);
    const float bn = bias[n];

    for (int b = 0; b < BB; b++) {
        const float* xr = g_s1 + (size_t)b * HH + lane * 24;
        float s = 0.f;
#pragma unroll
        for (int i = 0; i < 6; i++) {
            float4 xv = *(const float4*)(xr + i * 4);
            s += xv.x * wr[i].x + xv.y * wr[i].y + xv.z * wr[i].z + xv.w * wr[i].w;
        }
#pragma unroll
        for (int off = 16; off; off >>= 1) s += __shfl_xor_sync(0xffffffffu, s, off);
        if (lane == 0) g_s2[(size_t)b * HH + n] = fmaxf(s + bn, 0.f);
    }
}

__global__ void __launch_bounds__(256) k_final(const float* __restrict__ swo,
                                               const float* __restrict__ sbo,
                                               float* __restrict__ out)
{
    const int warp = threadIdx.x >> 5;
    const int lane = threadIdx.x & 31;
    const int b = blockIdx.x * 8 + warp;
    const float* xr = g_s2 + (size_t)b * HH + lane * 24;
    const float* wr = swo + lane * 24;
    float s = 0.f;
#pragma unroll
    for (int i = 0; i < 6; i++) {
        float4 xv = *(const float4*)(xr + i * 4);
        float4 wv = *(const float4*)(wr + i * 4);
        s += xv.x * wv.x + xv.y * wv.y + xv.z * wv.z + xv.w * wv.w;
    }
#pragma unroll
    for (int off = 16; off; off >>= 1) s += __shfl_xor_sync(0xffffffffu, s, off);
    if (lane == 0) out[b] = s + sbo[0];
}

// ---------------------------------------------------------------------------
extern "C" void kernel_launch(void* const* d_in, const int* in_sizes, int n_in,
                              void* d_out, int out_size)
{
    const int*   goal = (const int*)  d_in[0];
    const float* emb  = (const float*)d_in[1];
    const float* w_ih = (const float*)d_in[2];
    const float* w_hh = (const float*)d_in[3];
    const float* b_ih = (const float*)d_in[4];
    const float* b_hh = (const float*)d_in[5];
    const float* sw0  = (const float*)d_in[6];
    const float* sb0  = (const float*)d_in[7];
    const float* sw1  = (const float*)d_in[8];
    const float* sb1  = (const float*)d_in[9];
    const float* swo  = (const float*)d_in[10];
    const float* sbo  = (const float*)d_in[11];
    float* out = (float*)d_out;

    const int smem_rec = (HH * RCP + 2 * CHK * BB + BB * RC) * (int)sizeof(float); // 204.5KB
    cudaFuncSetAttribute(k_rec, cudaFuncAttributeMaxDynamicSharedMemorySize, smem_rec);
    cudaFuncSetAttribute(k_gi_tc, cudaFuncAttributeMaxDynamicSharedMemorySize, GI_SMEM);

    k_init<<<(BB * HH + 255) / 256, 256>>>();
    k_prep_w<<<(G3 * HH + 255) / 256, 256>>>(w_ih);
    k_prep_e<<<(int)(((size_t)VV * HH + 255) / 256), 256>>>(emb);
    k_gi_tc<<<dim3(G3 / 128, NSTEP), 256, GI_SMEM>>>(goal, b_ih);
    k_rec<<<RBLK, RTPB, smem_rec>>>(w_hh, b_hh);
    k_mlp0<<<HH / 8, 256>>>(sw0, sb0);
    k_mlp1<<<HH / 8, 256>>>(sw1, sb1);
    k_final<<<BB / 8, 256>>>(swo, sbo, out);
}

// round 15
// speedup vs baseline: 1.5759x; 1.2618x over previous
#include <cuda_runtime.h>
#include <cuda_bf16.h>
#include <math.h>
#include <stdint.h>

// Problem dims (fixed)
#define HH 768
#define G3 2304          // 3*H
#define BB 64            // batch
#define LL 512           // seq len
#define NSTEP 513        // 512 steps + final end-token step
#define NROWS (NSTEP*BB)

// recurrence kernel config (R7-proven, benched 7994us)
#define RBLK 128
#define RTPB 256
#define UPB  6
#define RC   18
#define RCP  24
#define CHK  256

// Scratch (device globals — allocation-free rule)
static __device__ __align__(256) float g_giT[(size_t)NROWS * G3];    // [l][unit][b]
static __device__ __align__(256) float g_hT[HH * BB];                // h transposed [k][b]
static __device__ __align__(256) float g_hbm[BB * HH];
static __device__ __align__(256) float g_s1[BB * HH];
static __device__ __align__(256) float g_s2[BB * HH];
static __device__ unsigned g_leaf[16];
static __device__ unsigned g_master = 0;
static __device__ unsigned g_gen    = 0;

// ---------------------------------------------------------------------------
// packed fp32 helpers (sm_103a f32x2)
__device__ __forceinline__ void ffma2(unsigned long long& d,
                                      unsigned long long a, unsigned long long b)
{
    asm("fma.rn.f32x2 %0, %1, %2, %0;" : "+l"(d) : "l"(a), "l"(b));
}
__device__ __forceinline__ unsigned long long pack2(float x)
{
    unsigned long long r;
    asm("mov.b64 %0, {%1, %1};" : "=l"(r) : "f"(x));
    return r;
}
__device__ __forceinline__ float2 unpk2(unsigned long long v)
{
    float2 f;
    asm("mov.b64 {%0, %1}, %2;" : "=f"(f.x), "=f"(f.y) : "l"(v));
    return f;
}
__device__ __forceinline__ void cpa16(unsigned dst, const void* src)
{
    asm volatile("cp.async.cg.shared.global [%0], [%1], 16;" :: "r"(dst), "l"(src));
}
__device__ __forceinline__ void cpa_commit() { asm volatile("cp.async.commit_group;" ::: "memory"); }
__device__ __forceinline__ void cpa_wait0()  { asm volatile("cp.async.wait_group 0;" ::: "memory"); }
__device__ __forceinline__ void cpa_wait1()  { asm volatile("cp.async.wait_group 1;" ::: "memory"); }

__device__ __forceinline__ float sigmoidf_(float x)
{
    return 1.f / (1.f + __expf(-x));
}

// ---------------------------------------------------------------------------
__global__ void k_init()
{
    int t = blockIdx.x * blockDim.x + threadIdx.x;
    if (t < BB * HH) g_hT[t] = 0.f;
}

// ---------------------------------------------------------------------------
// giT[l][unit][b] = relu_if_seq(emb[token(b,l)]) . w_ih[unit,:] + b_ih[unit]
// FMA-bound tile: 192 units x 64 batch per CTA, 128 threads.
// Thread tile: 8 batch (4 f32x2 pairs, packed dim) x 12 units (broadcast scalars).
// Per-SM-per-k: FFMA2 72 cyc > LDS 68 cyc -> FMA-bound (R7 was 64=64 balanced).
__global__ void __launch_bounds__(128) k_gi(const int* __restrict__ goal,
                                            const float* __restrict__ emb,
                                            const float* __restrict__ w_ih,
                                            const float* __restrict__ b_ih)
{
    __shared__ __align__(16) float As[16][192];   // units x k (transposed stage)
    __shared__ __align__(16) float Bs[16][64];    // batch x k
    __shared__ int tok[64];

    const int by  = blockIdx.y;        // step index
    const int n0  = blockIdx.x * 192;  // unit base
    const int tid = threadIdx.x;
    const bool seq = (by < LL);

    if (tid < 64) tok[tid] = seq ? goal[tid * LL + by] : 1;
    __syncthreads();

    const int bg = tid & 7;            // batch group -> batches bg*8..+7
    const int ug = tid >> 3;           // unit group  -> units  ug*12..+11

    float4 vw[6], ve[2];
    auto loadW = [&](float4 v[6], int k0) {
#pragma unroll
        for (int q = 0; q < 6; q++) {
            int f = tid + 128 * q;             // 0..767
            int r = f >> 2, kk = (f & 3) * 4;  // r 0..191
            v[q] = *(const float4*)(w_ih + (size_t)(n0 + r) * HH + k0 + kk);
        }
    };
    auto loadE = [&](float4 v[2], int k0) {
#pragma unroll
        for (int q = 0; q < 2; q++) {
            int f = tid + 128 * q;             // 0..255
            int r = f >> 2, kk = (f & 3) * 4;  // r 0..63
            v[q] = *(const float4*)(emb + (size_t)tok[r] * HH + k0 + kk);
            if (seq) {
                v[q].x = fmaxf(v[q].x, 0.f); v[q].y = fmaxf(v[q].y, 0.f);
                v[q].z = fmaxf(v[q].z, 0.f); v[q].w = fmaxf(v[q].w, 0.f);
            }
        }
    };
    auto storeW = [&](const float4 v[6]) {
#pragma unroll
        for (int q = 0; q < 6; q++) {
            int f = tid + 128 * q;
            int r = f >> 2, kk = (f & 3) * 4;
            As[kk][r] = v[q].x; As[kk+1][r] = v[q].y; As[kk+2][r] = v[q].z; As[kk+3][r] = v[q].w;
        }
    };
    auto storeE = [&](const float4 v[2]) {
#pragma unroll
        for (int q = 0; q < 2; q++) {
            int f = tid + 128 * q;
            int r = f >> 2, kk = (f & 3) * 4;
            Bs[kk][r] = v[q].x; Bs[kk+1][r] = v[q].y; Bs[kk+2][r] = v[q].z; Bs[kk+3][r] = v[q].w;
        }
    };

    unsigned long long acc[4][12];
#pragma unroll
    for (int p = 0; p < 4; p++)
#pragma unroll
        for (int c = 0; c < 12; c++) acc[p][c] = 0ull;

    loadW(vw, 0); loadE(ve, 0);
    storeW(vw);   storeE(ve);
    __syncthreads();

    for (int t = 0; t < HH / 16; t++) {
        float4 nw[6], ne[2];
        if (t < HH / 16 - 1) { loadW(nw, (t + 1) * 16); loadE(ne, (t + 1) * 16); }
#pragma unroll 2
        for (int k = 0; k < 16; k++) {
            ulonglong2 b0 = *(const ulonglong2*)&Bs[k][bg * 8];       // batches bg*8..+3
            ulonglong2 b1 = *(const ulonglong2*)&Bs[k][bg * 8 + 4];   // +4..+7
            float4 a0 = *(const float4*)&As[k][ug * 12];
            float4 a1 = *(const float4*)&As[k][ug * 12 + 4];
            float4 a2 = *(const float4*)&As[k][ug * 12 + 8];
            unsigned long long ap[4] = {b0.x, b0.y, b1.x, b1.y};
            unsigned long long bp[12] = {pack2(a0.x), pack2(a0.y), pack2(a0.z), pack2(a0.w),
                                         pack2(a1.x), pack2(a1.y), pack2(a1.z), pack2(a1.w),
                                         pack2(a2.x), pack2(a2.y), pack2(a2.z), pack2(a2.w)};
#pragma unroll
            for (int p = 0; p < 4; p++)
#pragma unroll
                for (int c = 0; c < 12; c++) ffma2(acc[p][c], ap[p], bp[c]);
        }
        __syncthreads();
        if (t < HH / 16 - 1) { storeW(nw); storeE(ne); }
        __syncthreads();
    }

    // epilogue: giT[(by*G3 + u)*64 + batch] (+ per-unit bias), batch-contiguous
#pragma unroll
    for (int c = 0; c < 12; c++) {
        const int u = n0 + ug * 12 + c;
        const float bias = b_ih[u];
        float2 v0 = unpk2(acc[0][c]);
        float2 v1 = unpk2(acc[1][c]);
        float2 v2 = unpk2(acc[2][c]);
        float2 v3 = unpk2(acc[3][c]);
        float* d = g_giT + ((size_t)by * G3 + u) * BB + bg * 8;
        *(float4*)(d)     = make_float4(v0.x + bias, v0.y + bias, v1.x + bias, v1.y + bias);
        *(float4*)(d + 4) = make_float4(v2.x + bias, v2.y + bias, v3.x + bias, v3.y + bias);
    }
}

// ---------------------------------------------------------------------------
// Two-level grid barrier (verbatim from benched 7994us kernel)
__device__ __forceinline__ void gsync(unsigned target)
{
    __syncthreads();
    if (threadIdx.x == 0) {
        unsigned old;
        asm volatile("atom.acq_rel.gpu.global.add.u32 %0, [%1], %2;"
                     : "=r"(old) : "l"(g_leaf + (blockIdx.x & 15u)), "r"(1u) : "memory");
        if ((old & 7u) == 7u) {
            unsigned o2;
            asm volatile("atom.acq_rel.gpu.global.add.u32 %0, [%1], %2;"
                         : "=r"(o2) : "l"(&g_master), "r"(1u) : "memory");
            if ((o2 & 15u) == 15u)
                asm volatile("st.release.gpu.global.u32 [%0], %1;"
                             :: "l"(&g_gen), "r"(target) : "memory");
        }
        unsigned g;
        do {
            asm volatile("ld.acquire.gpu.global.u32 %0, [%1];"
                         : "=r"(g) : "l"(&g_gen) : "memory");
        } while ((int)(g - target) < 0);
    }
    __syncthreads();
}

// ---------------------------------------------------------------------------
// Persistent recurrence (verbatim R7, benched 7994us)
__global__ void __launch_bounds__(RTPB, 1) k_rec(const float* __restrict__ w_hh,
                                                 const float* __restrict__ b_hh)
{
    extern __shared__ __align__(16) float sm[];
    float* ws  = sm;
    float* hs  = sm + HH * RCP;
    float* red = hs + CHK * BB;
    float* ghs = hs + 2 * CHK * BB;

    const int tid  = threadIdx.x;
    const int u0   = blockIdx.x * UPB;
    const int w    = tid >> 5;
    const int lane = tid & 31;
    const int rg   = lane & 15;
    const int cg   = lane >> 4;

    for (int idx = tid; idx < HH * RCP; idx += RTPB) {
        int k = idx / RCP, cc = idx - k * RCP;
        int g2 = cc / 12, c = cc - g2 * 12;
        float v = 0.f;
        if (c < 9) {
            int col = g2 * 9 + c;
            int gate = col / UPB, unit = col - gate * UPB;
            v = w_hh[(size_t)(gate * HH + u0 + unit) * HH + k];
        }
        ws[idx] = v;
    }
    float bh_r[2], bh_z[2], bh_n[2];
#pragma unroll
    for (int q = 0; q < 2; q++) {
        int t = tid + q * RTPB;
        if (t < BB * UPB) {
            int iu = t >> 6;
            bh_r[q] = b_hh[u0 + iu];
            bh_z[q] = b_hh[HH + u0 + iu];
            bh_n[q] = b_hh[2 * HH + u0 + iu];
        }
    }
    __syncthreads();

    const unsigned hsb = (unsigned)__cvta_generic_to_shared(hs);
    auto stage = [&](int ch) {
        const float4* src = (const float4*)(g_hT + (size_t)ch * CHK * BB) + tid;
        unsigned dst = hsb + (unsigned)((ch & 1) * (CHK * BB * 4)) + tid * 16;
#pragma unroll
        for (int j = 0; j < (CHK * BB / 4) / RTPB; j++)
            cpa16(dst + j * RTPB * 16, src + j * RTPB);
        cpa_commit();
    };

    const unsigned base = *(volatile unsigned*)&g_gen;
    unsigned ngen = 0;

    for (int l = 0; l < NSTEP; l++) {
        stage(0);
        stage(1);

        float pre_r[2], pre_z[2], pre_n[2], pre_h[2];
#pragma unroll
        for (int q = 0; q < 2; q++) {
            int t = tid + q * RTPB;
            if (t < BB * UPB) {
                int b = t & 63, iu = t >> 6;
                const float* gp = g_giT + ((size_t)l * G3 + u0 + iu) * BB + b;
                pre_r[q] = __ldcg(gp);
                pre_z[q] = __ldcg(gp + (size_t)HH * BB);
                pre_n[q] = __ldcg(gp + (size_t)2 * HH * BB);
                pre_h[q] = __ldcg(&g_hT[(u0 + iu) * BB + b]);
            }
        }

        unsigned long long acc[2][9];
#pragma unroll
        for (int p = 0; p < 2; p++)
#pragma unroll
            for (int c = 0; c < 9; c++) acc[p][c] = 0ull;

        for (int ch = 0; ch < HH / CHK; ch++) {
            if (ch < HH / CHK - 1) cpa_wait1(); else cpa_wait0();
            __syncthreads();
            const float* hb = hs + (ch & 1) * (CHK * BB);
            const int kb = w * (CHK / 8);
#pragma unroll 4
            for (int kk = 0; kk < CHK / 8; kk++) {
                const int kl = kb + kk;
                const int kg = ch * CHK + kl;
                ulonglong2 a = *(const ulonglong2*)&hb[kl * BB + rg * 4];
                const float* wp = &ws[kg * RCP + cg * 12];
                float4 w0 = *(const float4*)(wp);
                float4 w1 = *(const float4*)(wp + 4);
                float  w8 = wp[8];
                unsigned long long bp[9] = {pack2(w0.x), pack2(w0.y), pack2(w0.z), pack2(w0.w),
                                            pack2(w1.x), pack2(w1.y), pack2(w1.z), pack2(w1.w),
                                            pack2(w8)};
#pragma unroll
                for (int c = 0; c < 9; c++) {
                    ffma2(acc[0][c], a.x, bp[c]);
                    ffma2(acc[1][c], a.y, bp[c]);
                }
            }
            __syncthreads();
            if (ch == 0) stage(2);
        }

#pragma unroll
        for (int p = 0; p < 2; p++) {
            const int r0 = rg * 4 + 2 * p;
#pragma unroll
            for (int c = 0; c < 9; c++) {
                float2 v = unpk2(acc[p][c]);
                red[w * (BB * RC) + r0 * RC + cg * 9 + c]       = v.x;
                red[w * (BB * RC) + (r0 + 1) * RC + cg * 9 + c] = v.y;
            }
        }
        __syncthreads();
#pragma unroll
        for (int j = 0; j < 5; j++) {
            const int o = tid + j * RTPB;
            if (o < BB * RC) {
                float s = red[o];
#pragma unroll
                for (int ww = 1; ww < 8; ww++) s += red[ww * (BB * RC) + o];
                ghs[o] = s;
            }
        }
        __syncthreads();

#pragma unroll
        for (int q = 0; q < 2; q++) {
            const int t = tid + q * RTPB;
            if (t < BB * UPB) {
                const int b = t & 63, iu = t >> 6;
                float ghr = ghs[b * RC + iu];
                float ghz = ghs[b * RC + UPB + iu];
                float ghn = ghs[b * RC + 2 * UPB + iu];
                float r = sigmoidf_(pre_r[q] + ghr + bh_r[q]);
                float z = sigmoidf_(pre_z[q] + ghz + bh_z[q]);
                float n = tanhf(pre_n[q] + r * (ghn + bh_n[q]));
                float h = (1.f - z) * n + z * pre_h[q];
                if (l < LL) h = fmaxf(h, 0.f);     // final step NOT relu'd
                __stcg(&g_hT[(u0 + iu) * BB + b], h);
                if (l == LL) g_hbm[(size_t)b * HH + u0 + iu] = h;
            }
        }

        ++ngen;
        gsync(base + ngen);
    }
}

// ---------------------------------------------------------------------------
// Scorer (verbatim; device globals referenced in device code)
__global__ void __launch_bounds__(256) k_mlp0(const float* __restrict__ w,
                                              const float* __restrict__ bias)
{
    const int warp = threadIdx.x >> 5;
    const int lane = threadIdx.x & 31;
    const int n = blockIdx.x * 8 + warp;

    float4 wr[6];
    const float* wrow = w + (size_t)n * HH + lane * 24;
#pragma unroll
    for (int i = 0; i < 6; i++) wr[i] = *(const float4*)(wrow + i * 4);
    const float bn = bias[n];

    for (int b = 0; b < BB; b++) {
        const float* xr = g_hbm + (size_t)b * HH + lane * 24;
        float s = 0.f;
#pragma unroll
        for (int i = 0; i < 6; i++) {
            float4 xv = *(const float4*)(xr + i * 4);
            s += xv.x * wr[i].x + xv.y * wr[i].y + xv.z * wr[i].z + xv.w * wr[i].w;
        }
#pragma unroll
        for (int off = 16; off; off >>= 1) s += __shfl_xor_sync(0xffffffffu, s, off);
        if (lane == 0) g_s1[(size_t)b * HH + n] = fmaxf(s + bn, 0.f);
    }
}

__global__ void __launch_bounds__(256) k_mlp1(const float* __restrict__ w,
                                              const float* __restrict__ bias)
{
    const int warp = threadIdx.x >> 5;
    const int lane = threadIdx.x & 31;
    const int n = blockIdx.x * 8 + warp;

    float4 wr[6];
    const float* wrow = w + (size_t)n * HH + lane * 24;
#pragma unroll
    for (int i = 0; i < 6; i++) wr[i] = *(const float4*)(wrow + i * 4);
    const float bn = bias[n];

    for (int b = 0; b < BB; b++) {
        const float* xr = g_s1 + (size_t)b * HH + lane * 24;
        float s = 0.f;
#pragma unroll
        for (int i = 0; i < 6; i++) {
            float4 xv = *(const float4*)(xr + i * 4);
            s += xv.x * wr[i].x + xv.y * wr[i].y + xv.z * wr[i].z + xv.w * wr[i].w;
        }
#pragma unroll
        for (int off = 16; off; off >>= 1) s += __shfl_xor_sync(0xffffffffu, s, off);
        if (lane == 0) g_s2[(size_t)b * HH + n] = fmaxf(s + bn, 0.f);
    }
}

__global__ void __launch_bounds__(256) k_final(const float* __restrict__ swo,
                                               const float* __restrict__ sbo,
                                               float* __restrict__ out)
{
    const int warp = threadIdx.x >> 5;
    const int lane = threadIdx.x & 31;
    const int b = blockIdx.x * 8 + warp;
    const float* xr = g_s2 + (size_t)b * HH + lane * 24;
    const float* wr = swo + lane * 24;
    float s = 0.f;
#pragma unroll
    for (int i = 0; i < 6; i++) {
        float4 xv = *(const float4*)(xr + i * 4);
        float4 wv = *(const float4*)(wr + i * 4);
        s += xv.x * wv.x + xv.y * wv.y + xv.z * wv.z + xv.w * wv.w;
    }
#pragma unroll
    for (int off = 16; off; off >>= 1) s += __shfl_xor_sync(0xffffffffu, s, off);
    if (lane == 0) out[b] = s + sbo[0];
}

// ---------------------------------------------------------------------------
extern "C" void kernel_launch(void* const* d_in, const int* in_sizes, int n_in,
                              void* d_out, int out_size)
{
    const int*   goal = (const int*)  d_in[0];
    const float* emb  = (const float*)d_in[1];
    const float* w_ih = (const float*)d_in[2];
    const float* w_hh = (const float*)d_in[3];
    const float* b_ih = (const float*)d_in[4];
    const float* b_hh = (const float*)d_in[5];
    const float* sw0  = (const float*)d_in[6];
    const float* sb0  = (const float*)d_in[7];
    const float* sw1  = (const float*)d_in[8];
    const float* sb1  = (const float*)d_in[9];
    const float* swo  = (const float*)d_in[10];
    const float* sbo  = (const float*)d_in[11];
    float* out = (float*)d_out;

    const int smem_rec = (HH * RCP + 2 * CHK * BB + BB * RC) * (int)sizeof(float); // 204.5KB
    cudaFuncSetAttribute(k_rec, cudaFuncAttributeMaxDynamicSharedMemorySize, smem_rec);

    k_init<<<(BB * HH + 255) / 256, 256>>>();
    k_gi<<<dim3(G3 / 192, NSTEP), 128>>>(goal, emb, w_ih, b_ih);
    k_rec<<<RBLK, RTPB, smem_rec>>>(w_hh, b_hh);
    k_mlp0<<<HH / 8, 256>>>(sw0, sb0);
    k_mlp1<<<HH / 8, 256>>>(sw1, sb1);
    k_final<<<BB / 8, 256>>>(swo, sbo, out);
}